// round 1
// baseline (speedup 1.0000x reference)
#include <cuda_runtime.h>
#include <cstdint>

#define BN 4
#define GN 25
#define AN 147456          // 128*128*9
#define TOTN 147456
#define NUMPOS 73728
#define CAP 131072         // pos key capacity per batch (pow2, >= NUMPOS)
#define NBLK 576           // AN / 256
#define CHUNK 4096
#define NCHUNK (CAP / CHUNK)   // 32

#define FMW 128.0f
#define MIN_POS 0.15f
#define POS_TH 0.7f
#define NEG_TH 0.3f

// ------------------ static device scratch (no allocs allowed) ------------------
__device__ unsigned int       g_negmask[BN][AN];
__device__ int                g_blockNegSum[BN][NBLK];
__device__ int                g_blockNegOff[BN][NBLK];
__device__ int                g_negCount[BN];
__device__ int                g_posCount[BN];
__device__ unsigned long long g_posKeys[BN][CAP];
__device__ unsigned int       g_negbuf[BN][TOTN];

// ------------------ zero scratch each call (graph-replay determinism) ----------
__global__ void k_zero() {
    long long stride = (long long)gridDim.x * blockDim.x;
    long long t0 = (long long)blockIdx.x * blockDim.x + threadIdx.x;
    unsigned long long* pk = &g_posKeys[0][0];
    for (long long i = t0; i < (long long)BN * CAP; i += stride) pk[i] = 0ull;
    unsigned int* nb = &g_negbuf[0][0];
    for (long long i = t0; i < (long long)BN * TOTN; i += stride) nb[i] = 0u;
    if (t0 < BN) g_posCount[t0] = 0;
}

// ------------------ assignment: IoU, pos append, neg mask ---------------------
__global__ void k_assign(const float* __restrict__ anchors,
                         const float* __restrict__ gtb) {
    __shared__ float s_g[BN][GN][4];
    __shared__ float s_area[BN][GN];
    __shared__ int   s_red[256];

    int t = threadIdx.x;
    if (t < BN * GN) {
        int b = t / GN, g = t % GN;
        float x1 = __fmul_rn(gtb[(b * GN + g) * 4 + 0], 0.125f);
        float y1 = __fmul_rn(gtb[(b * GN + g) * 4 + 1], 0.125f);
        float x2 = __fmul_rn(gtb[(b * GN + g) * 4 + 2], 0.125f);
        float y2 = __fmul_rn(gtb[(b * GN + g) * 4 + 3], 0.125f);
        s_g[b][g][0] = x1; s_g[b][g][1] = y1; s_g[b][g][2] = x2; s_g[b][g][3] = y2;
        s_area[b][g] = __fmul_rn(__fsub_rn(x2, x1), __fsub_rn(y2, y1));
    }
    __syncthreads();

    int a = blockIdx.x * 256 + t;

    for (int b = 0; b < BN; b++) {
        const float4 av = *reinterpret_cast<const float4*>(
            anchors + (((long long)b * AN + a) << 2));
        float ax1 = av.x, ay1 = av.y, ax2 = av.z, ay2 = av.w;
        bool valid = (ax1 >= 0.0f) && (ay1 >= 0.0f) && (ax2 <= FMW) && (ay2 <= FMW);
        float areaA = __fmul_rn(__fsub_rn(ax2, ax1), __fsub_rn(ay2, ay1));

        float iou[GN];
        float rmax = 0.0f;
        #pragma unroll
        for (int g = 0; g < GN; g++) {
            float ltx = fmaxf(ax1, s_g[b][g][0]);
            float lty = fmaxf(ay1, s_g[b][g][1]);
            float rbx = fminf(ax2, s_g[b][g][2]);
            float rby = fminf(ay2, s_g[b][g][3]);
            float wx = fmaxf(__fsub_rn(rbx, ltx), 0.0f);
            float wy = fmaxf(__fsub_rn(rby, lty), 0.0f);
            float inter = __fmul_rn(wx, wy);
            float v = 0.0f;
            if (inter > 0.0f) {
                float uni = __fsub_rn(__fadd_rn(areaA, s_area[b][g]), inter);
                v = __fdiv_rn(inter, uni);
            }
            iou[g] = v;
            rmax = fmaxf(rmax, v);
        }

        unsigned nm = 0;
        int cnt = 0;
        #pragma unroll
        for (int g = 0; g < GN; g++) {
            float v = iou[g];
            bool pos = valid && (((v == rmax) && (v > MIN_POS)) || (v >= POS_TH));
            bool neg = valid && (v < NEG_TH) && !pos;
            if (pos) {
                int idx = atomicAdd(&g_posCount[b], 1);
                if (idx < CAP) {
                    unsigned flat = (unsigned)(a * GN + g);
                    unsigned long long key =
                        ((unsigned long long)__float_as_uint(v) << 32) |
                        (unsigned long long)(~flat);
                    g_posKeys[b][idx] = key;
                }
            }
            if (neg) { nm |= (1u << g); cnt++; }
        }
        g_negmask[b][a] = nm;

        s_red[t] = cnt;
        __syncthreads();
        for (int off = 128; off > 0; off >>= 1) {
            if (t < off) s_red[t] += s_red[t + off];
            __syncthreads();
        }
        if (t == 0) g_blockNegSum[b][blockIdx.x] = s_red[0];
        __syncthreads();
    }
}

// ------------------ scan of per-block neg counts ------------------------------
__global__ void k_scanblocks() {
    __shared__ int s[1024];
    int b = blockIdx.x, t = threadIdx.x;
    int v = (t < NBLK) ? g_blockNegSum[b][t] : 0;
    s[t] = v;
    __syncthreads();
    for (int off = 1; off < 1024; off <<= 1) {
        int x = (t >= off) ? s[t - off] : 0;
        __syncthreads();
        s[t] += x;
        __syncthreads();
    }
    if (t < NBLK) g_blockNegOff[b][t] = s[t] - v;
    if (t == NBLK - 1) g_negCount[b] = s[t];
}

// ------------------ scatter first TOT negs (ascending flat index) -------------
__global__ void k_negscatter() {
    __shared__ int s[256];
    int blk = blockIdx.x, t = threadIdx.x;
    int a = blk * 256 + t;
    for (int b = 0; b < BN; b++) {
        int boff = g_blockNegOff[b][blk];
        unsigned mask = g_negmask[b][a];
        int cnt = __popc(mask);
        __syncthreads();
        s[t] = cnt;
        __syncthreads();
        for (int off = 1; off < 256; off <<= 1) {
            int x = (t >= off) ? s[t - off] : 0;
            __syncthreads();
            s[t] += x;
            __syncthreads();
        }
        int excl = s[t] - cnt;
        if (boff < TOTN) {
            int r = boff + excl;
            unsigned mm = mask;
            while (mm && r < TOTN) {
                int g = __ffs(mm) - 1;
                mm &= mm - 1;
                g_negbuf[b][r] = (unsigned)(a * GN + g);
                r++;
            }
        }
    }
}

// ------------------ bitonic sort of pos keys (descending) ---------------------
// key = (iou_bits << 32) | ~flat  -> desc sort == iou desc, flat asc on ties.
// Zero keys (padding) sink to the tail.
__global__ void k_localsort() {
    __shared__ unsigned long long s[CHUNK];
    int b = blockIdx.x / NCHUNK, c = blockIdx.x % NCHUNK;
    unsigned long long* base = &g_posKeys[b][c * CHUNK];
    unsigned long long any = 0ull;
    for (int i = threadIdx.x; i < CHUNK; i += blockDim.x) {
        unsigned long long v = base[i];
        s[i] = v; any |= v;
    }
    if (!__syncthreads_or(any != 0ull)) return;  // all-padding chunk: nothing to do

    for (int k = 2; k <= CHUNK; k <<= 1) {
        for (int j = k >> 1; j > 0; j >>= 1) {
            for (int p = threadIdx.x; p < CHUNK / 2; p += blockDim.x) {
                int i = (p & (j - 1)) | ((p & ~(j - 1)) << 1);
                int l = i | j;
                int gi = c * CHUNK + i;
                bool desc = ((gi & k) == 0);
                unsigned long long x = s[i], y = s[l];
                if (desc ? (x < y) : (x > y)) { s[i] = y; s[l] = x; }
            }
            __syncthreads();
        }
    }
    for (int i = threadIdx.x; i < CHUNK; i += blockDim.x) base[i] = s[i];
}

__global__ void k_gstep(int k, int j) {
    int t = blockIdx.x * blockDim.x + threadIdx.x;
    const int PPB = CAP / 2;
    if (t >= BN * PPB) return;
    int b = t / PPB, p = t % PPB;
    int i = (p & (j - 1)) | ((p & ~(j - 1)) << 1);
    int l = i | j;
    unsigned long long x = g_posKeys[b][i];
    unsigned long long y = g_posKeys[b][l];
    if ((x | y) == 0ull) return;
    bool desc = ((i & k) == 0);
    if (desc ? (x < y) : (x > y)) { g_posKeys[b][i] = y; g_posKeys[b][l] = x; }
}

__global__ void k_lmerge(int k) {
    __shared__ unsigned long long s[CHUNK];
    int b = blockIdx.x / NCHUNK, c = blockIdx.x % NCHUNK;
    unsigned long long* base = &g_posKeys[b][c * CHUNK];
    unsigned long long any = 0ull;
    for (int i = threadIdx.x; i < CHUNK; i += blockDim.x) {
        unsigned long long v = base[i];
        s[i] = v; any |= v;
    }
    if (!__syncthreads_or(any != 0ull)) return;

    bool desc = (((c * CHUNK) & k) == 0);
    for (int j = CHUNK >> 1; j > 0; j >>= 1) {
        for (int p = threadIdx.x; p < CHUNK / 2; p += blockDim.x) {
            int i = (p & (j - 1)) | ((p & ~(j - 1)) << 1);
            int l = i | j;
            unsigned long long x = s[i], y = s[l];
            if (desc ? (x < y) : (x > y)) { s[i] = y; s[l] = x; }
        }
        __syncthreads();
    }
    for (int i = threadIdx.x; i < CHUNK; i += blockDim.x) base[i] = s[i];
}

// ------------------ final gather + offsets + output ---------------------------
__global__ void k_output(const float* __restrict__ anchors,
                         const float* __restrict__ gtb,
                         const int* __restrict__ cls,
                         float* __restrict__ out) {
    int t = blockIdx.x * blockDim.x + threadIdx.x;
    if (t >= BN * TOTN) return;
    int b = t / TOTN, j = t % TOTN;

    int P = g_posCount[b];
    int m = min(P, NUMPOS);

    unsigned flat;
    float obj;
    if (j < m) {
        unsigned long long key = g_posKeys[b][j];
        flat = ~((unsigned)key);
        obj = 1.0f;
    } else {
        flat = g_negbuf[b][j - m];
        obj = 0.0f;
    }

    int ai = (int)(flat / GN);
    int gi = (int)(flat % GN);

    const float4 av = *reinterpret_cast<const float4*>(
        anchors + (((long long)b * AN + ai) << 2));
    float ax1 = av.x, ay1 = av.y, ax2 = av.z, ay2 = av.w;

    const float* gp = gtb + (b * GN + gi) * 4;
    float gx1 = gp[0] * 0.125f, gy1 = gp[1] * 0.125f;
    float gx2 = gp[2] * 0.125f, gy2 = gp[3] * 0.125f;

    float acx = (ax1 + ax2) * 0.5f, acy = (ay1 + ay2) * 0.5f;
    float aw = ax2 - ax1, ah = ay2 - ay1;
    float gcx = (gx1 + gx2) * 0.5f, gcy = (gy1 + gy2) * 0.5f;
    float gw = gx2 - gx1, gh = gy2 - gy1;

    float tx = (gcx - acx) / aw;
    float ty = (gcy - acy) / ah;
    float tw = logf(gw / aw);
    float th = logf(gh / ah);

    long long r = (long long)b * TOTN + j;
    const long long O_OBJ = (long long)BN * TOTN * 4;
    const long long O_CLS = O_OBJ + (long long)BN * TOTN;
    const long long O_OFF = O_CLS + (long long)BN * TOTN;

    out[r * 4 + 0] = ax1;
    out[r * 4 + 1] = ay1;
    out[r * 4 + 2] = ax2;
    out[r * 4 + 3] = ay2;
    out[O_OBJ + r] = obj;
    out[O_CLS + r] = (float)cls[b * GN + gi];
    out[O_OFF + r * 4 + 0] = tx;
    out[O_OFF + r * 4 + 1] = ty;
    out[O_OFF + r * 4 + 2] = tw;
    out[O_OFF + r * 4 + 3] = th;
}

// ------------------------------------------------------------------------------
extern "C" void kernel_launch(void* const* d_in, const int* in_sizes, int n_in,
                              void* d_out, int out_size) {
    const float* anchors = (const float*)d_in[0];
    const float* gtb     = (const float*)d_in[1];
    const int*   cls     = (const int*)d_in[2];
    float*       out     = (float*)d_out;

    k_zero<<<1024, 256>>>();
    k_assign<<<NBLK, 256>>>(anchors, gtb);
    k_scanblocks<<<BN, 1024>>>();
    k_negscatter<<<NBLK, 256>>>();

    k_localsort<<<BN * NCHUNK, 512>>>();
    for (int k = CHUNK * 2; k <= CAP; k <<= 1) {
        for (int j = k >> 1; j >= CHUNK; j >>= 1) {
            k_gstep<<<(BN * (CAP / 2) + 255) / 256, 256>>>(k, j);
        }
        k_lmerge<<<BN * NCHUNK, 512>>>(k);
    }

    k_output<<<(BN * TOTN + 255) / 256, 256>>>(anchors, gtb, cls, out);
}